// round 4
// baseline (speedup 1.0000x reference)
#include <cuda_runtime.h>

// Binarization (braq high_order_residual, ORDER=2)
// x:    (11008, 4096) float32
// mask: (11008, 4096) int32  (0/1 — jnp bool materialized as int32 by harness)
// out:  (11008, 4096) float32
//
// One block per row. Row data lives in registers (256 thr x 16 elems).
// 5 block reductions produce the 4 row scalars; output is a closed form.

static constexpr int ROWS    = 11008;
static constexpr int COLS    = 4096;
static constexpr int THREADS = 256;
static constexpr int ITEMS   = COLS / (THREADS * 4);   // 4 vec4 groups per thread

__device__ __forceinline__ float block_reduce(float v, float* sh) {
    #pragma unroll
    for (int o = 16; o > 0; o >>= 1)
        v += __shfl_down_sync(0xffffffffu, v, o);
    const int lane = threadIdx.x & 31;
    const int wid  = threadIdx.x >> 5;
    if (lane == 0) sh[wid] = v;
    __syncthreads();
    if (wid == 0) {
        v = (lane < (THREADS / 32)) ? sh[lane] : 0.0f;
        #pragma unroll
        for (int o = 4; o > 0; o >>= 1)
            v += __shfl_down_sync(0xffffffffu, v, o);
        if (lane == 0) sh[0] = v;
    }
    __syncthreads();
    float r = sh[0];
    __syncthreads();
    return r;
}

__device__ __forceinline__ float signf(float c) {
    // matches jnp.sign: sign(0) = 0
    return (c > 0.0f) ? 1.0f : ((c < 0.0f) ? -1.0f : 0.0f);
}

__global__ void __launch_bounds__(THREADS)
binarize_kernel(const float4* __restrict__ x,
                const int4*   __restrict__ mask,
                float4*       __restrict__ out) {
    __shared__ float sh[THREADS / 32];

    const size_t base = (size_t)blockIdx.x * (COLS / 4);
    const float4* xr   = x    + base;
    const int4*   mr   = mask + base;
    float4*       orow = out  + base;

    float        xm[ITEMS][4];   // masked x (0 outside mask)
    unsigned int mk[ITEMS];      // 4 predicate bits per item (bit e = elem e)

    // ---- pass 0: load, masked sum + count ----
    float s = 0.0f, c = 0.0f;
    #pragma unroll
    for (int j = 0; j < ITEMS; j++) {
        const int idx = threadIdx.x + j * THREADS;
        const float4 xv = __ldcs(&xr[idx]);
        const int4   mv = __ldcs(&mr[idx]);
        unsigned int bits = 0;
        if (mv.x) bits |= 1u;
        if (mv.y) bits |= 2u;
        if (mv.z) bits |= 4u;
        if (mv.w) bits |= 8u;
        mk[j] = bits;
        xm[j][0] = (bits & 1u) ? xv.x : 0.0f;
        xm[j][1] = (bits & 2u) ? xv.y : 0.0f;
        xm[j][2] = (bits & 4u) ? xv.z : 0.0f;
        xm[j][3] = (bits & 8u) ? xv.w : 0.0f;
        s += xm[j][0] + xm[j][1] + xm[j][2] + xm[j][3];
        c += (float)__popc(bits);
    }

    const float sum1 = block_reduce(s, sh);
    const float cnt  = block_reduce(c, sh);
    const float inv  = 1.0f / fmaxf(cnt, 1.0f);
    const float mean1 = sum1 * inv;     // cnt==0 => sum1==0 => mean1==0

    // ---- pass 1: scale1 = mean |x - mean1| over mask ----
    float a1 = 0.0f;
    #pragma unroll
    for (int j = 0; j < ITEMS; j++) {
        const unsigned int bits = mk[j];
        #pragma unroll
        for (int e = 0; e < 4; e++)
            if (bits & (1u << e)) a1 += fabsf(xm[j][e] - mean1);
    }
    const float scale1 = block_reduce(a1, sh) * inv;

    // ---- pass 2: mean2 of residual2 = c1 - sign(c1)*scale1 over mask ----
    float s2 = 0.0f;
    #pragma unroll
    for (int j = 0; j < ITEMS; j++) {
        const unsigned int bits = mk[j];
        #pragma unroll
        for (int e = 0; e < 4; e++) {
            if (bits & (1u << e)) {
                const float c1 = xm[j][e] - mean1;
                s2 += c1 - signf(c1) * scale1;
            }
        }
    }
    const float mean2 = block_reduce(s2, sh) * inv;

    // ---- pass 3: scale2 = mean |residual2 - mean2| over mask ----
    float a2 = 0.0f;
    #pragma unroll
    for (int j = 0; j < ITEMS; j++) {
        const unsigned int bits = mk[j];
        #pragma unroll
        for (int e = 0; e < 4; e++) {
            if (bits & (1u << e)) {
                const float c1 = xm[j][e] - mean1;
                const float r2 = c1 - signf(c1) * scale1;
                a2 += fabsf(r2 - mean2);
            }
        }
    }
    const float scale2 = block_reduce(a2, sh) * inv;

    // ---- output: binary1 + binary2 inside mask, 0 outside ----
    #pragma unroll
    for (int j = 0; j < ITEMS; j++) {
        const int idx = threadIdx.x + j * THREADS;
        const unsigned int bits = mk[j];
        float4 o;
        float* op = &o.x;
        #pragma unroll
        for (int e = 0; e < 4; e++) {
            float v = 0.0f;
            if (bits & (1u << e)) {
                const float c1 = xm[j][e] - mean1;
                const float r2 = c1 - signf(c1) * scale1;
                const float c2 = r2 - mean2;
                v = signf(c1) * scale1 + mean1 + signf(c2) * scale2 + mean2;
            }
            op[e] = v;
        }
        __stcs(&orow[idx], o);
    }
}

extern "C" void kernel_launch(void* const* d_in, const int* in_sizes, int n_in,
                              void* d_out, int out_size) {
    const float4* x = (const float4*)d_in[0];
    const int4*   m = (const int4*)d_in[1];
    float4*       o = (float4*)d_out;
    binarize_kernel<<<ROWS, THREADS>>>(x, m, o);
}

// round 7
// speedup vs baseline: 1.4294x; 1.4294x over previous
#include <cuda_runtime.h>

// Binarization (braq high_order_residual, ORDER=2)
// x: (11008,4096) f32, mask: (11008,4096) int32 (0/1), out: (11008,4096) f32
//
// One block per row, row in registers. Inner passes are UNGATED; unmasked
// lanes (xm=0) contribute row-constant terms removed by closed-form
// corrections using the block-wide unmasked count U. Mask bits kept as one
// 16-bit field per thread, tested only in the final gated store.

static constexpr int ROWS    = 11008;
static constexpr int COLS    = 4096;
static constexpr int THREADS = 256;
static constexpr int VEC     = COLS / (THREADS * 4);   // 4 float4 per thread

// reduce two floats across the block in one barrier round
__device__ __forceinline__ float2 block_reduce2(float a, float b, float2* sh) {
    #pragma unroll
    for (int o = 16; o > 0; o >>= 1) {
        a += __shfl_down_sync(0xffffffffu, a, o);
        b += __shfl_down_sync(0xffffffffu, b, o);
    }
    const int lane = threadIdx.x & 31;
    const int wid  = threadIdx.x >> 5;
    if (lane == 0) sh[wid] = make_float2(a, b);
    __syncthreads();
    if (wid == 0) {
        float2 v = (lane < (THREADS / 32)) ? sh[lane] : make_float2(0.f, 0.f);
        a = v.x; b = v.y;
        #pragma unroll
        for (int o = 4; o > 0; o >>= 1) {
            a += __shfl_down_sync(0xffffffffu, a, o);
            b += __shfl_down_sync(0xffffffffu, b, o);
        }
        if (lane == 0) sh[0] = make_float2(a, b);
    }
    __syncthreads();
    float2 r = sh[0];
    __syncthreads();
    return r;
}

__global__ void __launch_bounds__(THREADS)
binarize_kernel(const float4* __restrict__ x,
                const int4*   __restrict__ mask,
                float4*       __restrict__ out) {
    __shared__ float2 sh[THREADS / 32];

    const size_t base = (size_t)blockIdx.x * (COLS / 4);
    const float4* xr   = x    + base;
    const int4*   mr   = mask + base;
    float4*       orow = out  + base;

    float t[VEC][4];          // xm, later overwritten with c1
    unsigned int mk = 0;      // 16 mask bits (bit j*4+e)

    // ---- pass 0: load, masked values, sum, count ----
    float s = 0.0f;
    #pragma unroll
    for (int j = 0; j < VEC; j++) {
        const int idx = threadIdx.x + j * THREADS;
        const float4 xv = __ldcs(&xr[idx]);
        const int4   mv = __ldcs(&mr[idx]);
        float v0 = mv.x ? xv.x : 0.0f; if (mv.x) mk |= 1u << (j * 4 + 0);
        float v1 = mv.y ? xv.y : 0.0f; if (mv.y) mk |= 1u << (j * 4 + 1);
        float v2 = mv.z ? xv.z : 0.0f; if (mv.z) mk |= 1u << (j * 4 + 2);
        float v3 = mv.w ? xv.w : 0.0f; if (mv.w) mk |= 1u << (j * 4 + 3);
        t[j][0] = v0; t[j][1] = v1; t[j][2] = v2; t[j][3] = v3;
        s += (v0 + v1) + (v2 + v3);
    }
    const float cthr = (float)__popc(mk);

    const float2 r0   = block_reduce2(s, cthr, sh);
    const float  sum1 = r0.x;
    const float  cnt  = r0.y;
    const float  inv  = 1.0f / fmaxf(cnt, 1.0f);
    const float  mean1 = sum1 * inv;                 // cnt==0 -> 0
    const float  U    = (float)COLS - cnt;           // unmasked count (row)

    // ---- pass A (ungated): a1 = sum|c1|, sg = sum sign(c1); cache c1 ----
    float a1 = 0.0f, sg = 0.0f;
    #pragma unroll
    for (int j = 0; j < VEC; j++) {
        #pragma unroll
        for (int e = 0; e < 4; e++) {
            const float c1 = t[j][e] - mean1;
            t[j][e] = c1;
            a1 += fabsf(c1);
            if (c1 > 0.0f) sg += 1.0f; else if (c1 < 0.0f) sg -= 1.0f;
        }
    }
    const float2 rA = block_reduce2(a1, sg, sh);

    // corrections: unmasked lane has c1 = -mean1
    const float sgn1   = (mean1 > 0.0f) ? 1.0f : ((mean1 < 0.0f) ? -1.0f : 0.0f);
    const float scale1 = (rA.x - U * fabsf(mean1)) * inv;
    const float sgm    = rA.y + U * sgn1;
    const float mean2  = -scale1 * sgm * inv;        // since sum_mask(c1) == 0

    // unmasked residual2 constant and its pass-B contribution
    const float r2u = -mean1 + sgn1 * scale1;
    const float K   = fabsf(r2u - mean2);

    // ---- pass B (ungated): a2 = sum|r2 - mean2| ----
    float a2 = 0.0f;
    #pragma unroll
    for (int j = 0; j < VEC; j++) {
        #pragma unroll
        for (int e = 0; e < 4; e++) {
            const float c1 = t[j][e];
            const float d  = (c1 > 0.0f) ? scale1 : ((c1 < 0.0f) ? -scale1 : 0.0f);
            const float r2 = c1 - d;
            a2 += fabsf(r2 - mean2);
        }
    }
    const float2 rB = block_reduce2(a2, 0.0f, sh);
    const float scale2 = (rB.x - U * K) * inv;
    const float M = mean1 + mean2;

    // ---- output: (binary1 + binary2) inside mask, 0 outside ----
    #pragma unroll
    for (int j = 0; j < VEC; j++) {
        const int idx = threadIdx.x + j * THREADS;
        float4 o;
        float* op = &o.x;
        #pragma unroll
        for (int e = 0; e < 4; e++) {
            const float c1 = t[j][e];
            const float d  = (c1 > 0.0f) ? scale1 : ((c1 < 0.0f) ? -scale1 : 0.0f);
            const float r2 = c1 - d;
            const float c2 = r2 - mean2;
            const float d2 = (c2 > 0.0f) ? scale2 : ((c2 < 0.0f) ? -scale2 : 0.0f);
            const float v  = (d + d2) + M;
            op[e] = (mk & (1u << (j * 4 + e))) ? v : 0.0f;
        }
        __stcs(&orow[idx], o);
    }
}

extern "C" void kernel_launch(void* const* d_in, const int* in_sizes, int n_in,
                              void* d_out, int out_size) {
    const float4* x = (const float4*)d_in[0];
    const int4*   m = (const int4*)d_in[1];
    float4*       o = (float4*)d_out;
    binarize_kernel<<<ROWS, THREADS>>>(x, m, o);
}